// round 3
// baseline (speedup 1.0000x reference)
#include <cuda_runtime.h>
#include <string.h>

// Correlation layer: B=4, C=256, H=64, W=96, 21x21 displacements stride 2, pad 20.
// out[b][dy*21+dx][y][x] = (1/256) * sum_c in1[b][c][y][x] * in2[b][c][y+2dy-20][x+2dx-20]
// (zero outside bounds)

#define BATCH 4
#define CH    256
#define HH    64
#define WW    96
#define NDY   21
#define NDX   21
#define CC    8            // channels per smem chunk
#define PADW  162          // padded row width in words (>=136, even, ==2 mod 32 for banks)
#define P     8            // x pixels per thread
#define NXI   12           // threads along x (12*8 = 96)
#define NWARPS 9
#define NTHREADS 288       // 9 warps; 252 active compute threads (12 xi * 21 dy)

typedef unsigned long long ull;

__device__ __forceinline__ ull ffma2(ull a, ull b, ull c) {
    ull d;
    asm("fma.rn.f32x2 %0, %1, %2, %3;" : "=l"(d) : "l"(a), "l"(b), "l"(c));
    return d;
}

__device__ __forceinline__ float2 u2f(ull v) {
    float2 f;
    memcpy(&f, &v, 8);
    return f;
}

extern __shared__ float smem[];

__global__ void __launch_bounds__(NTHREADS, 1)
corr_kernel(const float* __restrict__ in1, const float* __restrict__ in2,
            float* __restrict__ out)
{
    // smem layout: s2[CC][NDY][PADW], then s1[CC][WW]
    float* s2 = smem;
    float* s1 = smem + CC * NDY * PADW;

    const int y0 = blockIdx.x;          // 0..63
    const int b  = blockIdx.y;          // 0..3
    const int tid  = threadIdx.x;
    const int wrp  = tid >> 5;          // 0..8
    const int lane = tid & 31;

    // Warp-internal layout chosen for conflict-free LDS:
    //   u = lane/8 in 0..3, i = lane%8 in 0..7
    //   xi = u + 4*a (a = warp%3), dy = i + 8*bg (bg = warp/3)
    const int u  = lane >> 3;
    const int i  = lane & 7;
    const int a  = wrp % 3;
    const int bg = wrp / 3;
    const int xi = u + 4 * a;           // 0..11
    const int dy = i + 8 * bg;          // 0..23 (>=21 inactive)
    const bool act = (dy < NDY);
    const int xbase = xi * P;           // first x owned by this thread

    // Accumulators: acc[dx][j] holds packed (x pair) sums, j=0..3 -> x offsets {0,1},{2,3},{4,5},{6,7}
    ull acc[NDX][4];
#pragma unroll
    for (int d = 0; d < NDX; ++d) {
#pragma unroll
        for (int j = 0; j < 4; ++j) acc[d][j] = 0ull;
    }

    for (int cc = 0; cc < CH / CC; ++cc) {
        const int c0 = cc * CC;
        __syncthreads();   // protect smem from previous chunk's readers

        // ---- fill s1: in1[b][c0+c][y0][0..95] ----
        for (int j = tid; j < CC * WW; j += NTHREADS) {
            const int c = j / WW;
            const int x = j - c * WW;
            s1[j] = in1[(((b * CH + c0 + c) * HH) + y0) * WW + x];
        }

        // ---- fill s2: shifted/zero-padded rows of in2 ----
        // row r = c*NDY + dyr ; word w holds in2[...][y0+2dyr-20][w-20] (0 outside)
        for (int r = wrp; r < CC * NDY; r += NWARPS) {
            const int c   = r / NDY;
            const int dyr = r - c * NDY;
            const int y2  = y0 + 2 * dyr - 20;
            const bool vy = ((unsigned)y2 < (unsigned)HH);
            const float* src = in2 + (((b * CH + c0 + c) * HH) + y2) * WW;
            float* dst = s2 + r * PADW;
#pragma unroll
            for (int k = 0; k < 6; ++k) {
                const int widx = lane + 32 * k;
                if (widx < PADW) {
                    const int x2 = widx - 20;
                    float v = 0.0f;
                    if (vy && (unsigned)x2 < (unsigned)WW) v = src[x2];
                    dst[widx] = v;
                }
            }
        }
        __syncthreads();

        if (act) {
#pragma unroll 1
            for (int c = 0; c < CC; ++c) {
                // q: 8 floats of in1 for this thread's x range (packed pairs)
                const ull* qu = (const ull*)(s1 + c * WW + xbase);
                const ull qp0 = qu[0], qp1 = qu[1], qp2 = qu[2], qp3 = qu[3];

                // shifted row for this thread's dy; window = 4 pairs starting at pair (xbase/2 + dx)
                const ull* row_u = (const ull*)(s2 + (c * NDY + dy) * PADW) + (xbase >> 1);

                ull w0 = row_u[0], w1 = row_u[1], w2 = row_u[2], w3 = row_u[3];
#pragma unroll
                for (int dx = 0; dx < NDX; ++dx) {
                    acc[dx][0] = ffma2(qp0, w0, acc[dx][0]);
                    acc[dx][1] = ffma2(qp1, w1, acc[dx][1]);
                    acc[dx][2] = ffma2(qp2, w2, acc[dx][2]);
                    acc[dx][3] = ffma2(qp3, w3, acc[dx][3]);
                    if (dx < NDX - 1) {
                        w0 = w1; w1 = w2; w2 = w3;
                        w3 = row_u[dx + 4];
                    }
                }
            }
        }
    }

    // ---- store: out[b][dy*21+dx][y0][xbase..xbase+7], scaled by 1/256 ----
    if (act) {
        const float scale = 1.0f / 256.0f;
#pragma unroll
        for (int dx = 0; dx < NDX; ++dx) {
            float2 f0 = u2f(acc[dx][0]);
            float2 f1 = u2f(acc[dx][1]);
            float2 f2 = u2f(acc[dx][2]);
            float2 f3 = u2f(acc[dx][3]);
            float4 o0 = make_float4(f0.x * scale, f0.y * scale, f1.x * scale, f1.y * scale);
            float4 o1 = make_float4(f2.x * scale, f2.y * scale, f3.x * scale, f3.y * scale);
            float* dst = out + ((size_t)(b * (NDY * NDX) + dy * NDX + dx) * HH + y0) * WW + xbase;
            ((float4*)dst)[0] = o0;
            ((float4*)dst)[1] = o1;
        }
    }
}

extern "C" void kernel_launch(void* const* d_in, const int* in_sizes, int n_in,
                              void* d_out, int out_size)
{
    const float* in1 = (const float*)d_in[0];
    const float* in2 = (const float*)d_in[1];
    float* out = (float*)d_out;

    const int smem_bytes = (CC * NDY * PADW + CC * WW) * (int)sizeof(float); // ~112 KB
    cudaFuncSetAttribute(corr_kernel, cudaFuncAttributeMaxDynamicSharedMemorySize, smem_bytes);

    dim3 grid(HH, BATCH);   // (y, b) = 64 x 4 = 256 blocks
    corr_kernel<<<grid, NTHREADS, smem_bytes>>>(in1, in2, out);
}

// round 10
// speedup vs baseline: 3.5899x; 3.5899x over previous
#include <cuda_runtime.h>
#include <string.h>

// Correlation: B=4, C=256, H=64, W=96, 21x21 displacements stride 2, pad 20.
// out[b][dy*21+dx][y][x] = (1/256) * sum_c in1[b][c][y][x] * in2[b][c][y+2dy-20][x+2dx-20]

#define BATCH 4
#define CH    256
#define HH    64
#define WW    96
#define NDY   21
#define NDX   21
#define CC    8              // channels per smem chunk
#define NCHUNK (CH / CC)     // 32
#define PADW  138            // padded row width in words (even; 138*4=552B: 8B-aligned rows)
#define P     16             // x pixels per thread
#define NDXH  11             // dx per thread (halves 0..10 and 10..20, dx=10 duplicated)
#define NTHREADS 256
#define NACT  252            // 6 xi * 21 dy * 2 dxh

#define S2_ROWS   (CC * NDY)              // 168
#define S2_WORDS  (S2_ROWS * PADW)        // 23184 (x4 = 92736 B, 16B-aligned)
#define S1_WORDS  (CC * WW)               // 768
#define BUF_WORDS (S2_WORDS + S1_WORDS)   // 23952
#define SMEM_BYTES (2 * BUF_WORDS * 4)    // 191616

typedef unsigned long long ull;

__device__ __forceinline__ ull ffma2(ull a, ull b, ull c) {
    ull d;
    asm("fma.rn.f32x2 %0, %1, %2, %3;" : "=l"(d) : "l"(a), "l"(b), "l"(c));
    return d;
}
__device__ __forceinline__ float2 u2f(ull v) { float2 f; memcpy(&f, &v, 8); return f; }

__device__ __forceinline__ void cp_async16(unsigned int dst, const void* src, unsigned int sbytes) {
    asm volatile("cp.async.ca.shared.global [%0], [%1], 16, %2;"
                 :: "r"(dst), "l"(src), "r"(sbytes) : "memory");
}
__device__ __forceinline__ void cp_async8(unsigned int dst, const void* src, unsigned int sbytes) {
    asm volatile("cp.async.ca.shared.global [%0], [%1], 8, %2;"
                 :: "r"(dst), "l"(src), "r"(sbytes) : "memory");
}
__device__ __forceinline__ void cp_commit() { asm volatile("cp.async.commit_group;" ::: "memory"); }
__device__ __forceinline__ void cp_wait0()  { asm volatile("cp.async.wait_group 0;" ::: "memory"); }

extern __shared__ float smem[];

// Issue cp.async fills for channel chunk cc into buffer `buf`.
// s2 interior: words [20,116) of each row (24 vec4 tiles). Even rows (16B-aligned
// dst) use 16B cp.async; odd rows use 2x 8B. s1 (16B-aligned) uses 16B.
__device__ __forceinline__ void issue_fill(int buf, int cc, int b, int y0,
                                           const float* __restrict__ in1,
                                           const float* __restrict__ in2,
                                           unsigned int smem_u32, int tid)
{
    const int c0 = cc * CC;
    const unsigned int base = smem_u32 + (unsigned int)(buf * BUF_WORDS) * 4u;
    const int NS2 = S2_ROWS * 24;            // 4032 vec4 tiles
    const int TOT = NS2 + CC * 24;           // + 192 for s1
    for (int t = tid; t < TOT; t += NTHREADS) {
        if (t < NS2) {
            const int row = t / 24;
            const int k   = t - row * 24;          // vec4 index; word = 20 + 4k
            const int c   = row / NDY;
            const int dyr = row - c * NDY;
            const int y2  = y0 + 2 * dyr - 20;
            const bool vy = ((unsigned)y2 < (unsigned)HH);
            const int y2c = vy ? y2 : 0;
            const float* src = in2 + (((size_t)(b * CH + c0 + c) * HH) + y2c) * WW + 4 * k;
            const unsigned int dst = base + (unsigned int)(row * PADW + 20 + 4 * k) * 4u;
            if (row & 1) {
                cp_async8(dst,      src,     vy ? 8u : 0u);
                cp_async8(dst + 8u, src + 2, vy ? 8u : 0u);
            } else {
                cp_async16(dst, src, vy ? 16u : 0u);
            }
        } else {
            const int j = t - NS2;
            const int c = j / 24;
            const int k = j - c * 24;
            const float* src = in1 + (((size_t)(b * CH + c0 + c) * HH) + y0) * WW + 4 * k;
            const unsigned int dst = base + (unsigned int)(S2_WORDS + c * WW + 4 * k) * 4u;
            cp_async16(dst, src, 16u);
        }
    }
    cp_commit();
}

__global__ void __launch_bounds__(NTHREADS, 1)
corr_kernel(const float* __restrict__ in1, const float* __restrict__ in2,
            float* __restrict__ out)
{
    const int y0 = blockIdx.x;          // 0..63
    const int b  = blockIdx.y;          // 0..3
    const int tid = threadIdx.x;

    unsigned int smem_u32;
    {
        void* p = smem;
        smem_u32 = (unsigned int)__cvta_generic_to_shared(p);
    }

    // compute-thread mapping (dy fastest)
    const bool act = (tid < NACT);
    const int tt   = act ? tid : (NACT - 1);
    const int dxh  = tt / 126;           // 0 or 1
    const int r    = tt - dxh * 126;
    const int xi   = r / NDY;            // 0..5
    const int dy   = r - xi * NDY;       // 0..20
    const int xbase = xi * P;            // 0,16,...,80
    const int dx0   = 10 * dxh;          // dx range [dx0, dx0+10]

    // ---- prologue: zero pad columns of both buffers (words [0,20) and [116,138)) ----
    {
        const int PADW_CNT = 42;                       // 20 left + 22 right
        const int TOTZ = 2 * S2_ROWS * PADW_CNT;       // 14112
        for (int t = tid; t < TOTZ; t += NTHREADS) {
            const int buf = t / (S2_ROWS * PADW_CNT);
            const int rr  = t - buf * (S2_ROWS * PADW_CNT);
            const int row = rr / PADW_CNT;
            const int pw  = rr - row * PADW_CNT;
            const int w   = (pw < 20) ? pw : (pw + 96); // 20..41 -> 116..137
            smem[buf * BUF_WORDS + row * PADW + w] = 0.0f;
        }
    }

    // accumulators: acc[dx][j], j = pair index (x = xbase+2j, xbase+2j+1)
    ull acc[NDXH][8];
#pragma unroll
    for (int d = 0; d < NDXH; ++d)
#pragma unroll
        for (int j = 0; j < 8; ++j) acc[d][j] = 0ull;

    issue_fill(0, 0, b, y0, in1, in2, smem_u32, tid);

    for (int cc = 0; cc < NCHUNK; ++cc) {
        cp_wait0();
        __syncthreads();                      // chunk cc visible; buffer (cc+1)&1 free
        if (cc + 1 < NCHUNK)
            issue_fill((cc + 1) & 1, cc + 1, b, y0, in1, in2, smem_u32, tid);

        const float* s2b = smem + (cc & 1) * BUF_WORDS;
        const float* s1b = s2b + S2_WORDS;

        if (act) {
#pragma unroll 1
            for (int c = 0; c < CC; ++c) {
                const ull* qs = (const ull*)(s1b + c * WW) + (xbase >> 1);
                ull q[8];
#pragma unroll
                for (int j = 0; j < 8; ++j) q[j] = qs[j];

                const ull* rp = (const ull*)(s2b + (c * NDY + dy) * PADW) + (xbase >> 1) + dx0;
                ull w[8];
#pragma unroll
                for (int j = 0; j < 8; ++j) w[j] = rp[j];

#pragma unroll
                for (int dx = 0; dx < NDXH; ++dx) {
#pragma unroll
                    for (int j = 0; j < 8; ++j)
                        acc[dx][j] = ffma2(q[j], w[(dx + j) & 7], acc[dx][j]);
                    if (dx < NDXH - 1)
                        w[dx & 7] = rp[dx + 8];
                }
            }
        }
    }

    // ---- store ----
    if (act) {
        const float scale = 1.0f / 256.0f;
#pragma unroll
        for (int dx = 0; dx < NDXH; ++dx) {
            const int d = dy * NDX + dx0 + dx;
            float* dst = out + ((size_t)(b * (NDY * NDX) + d) * HH + y0) * WW + xbase;
#pragma unroll
            for (int g = 0; g < 4; ++g) {
                float2 f0 = u2f(acc[dx][2 * g]);
                float2 f1 = u2f(acc[dx][2 * g + 1]);
                ((float4*)dst)[g] = make_float4(f0.x * scale, f0.y * scale,
                                                f1.x * scale, f1.y * scale);
            }
        }
    }
}

extern "C" void kernel_launch(void* const* d_in, const int* in_sizes, int n_in,
                              void* d_out, int out_size)
{
    const float* in1 = (const float*)d_in[0];
    const float* in2 = (const float*)d_in[1];
    float* out = (float*)d_out;

    cudaFuncSetAttribute(corr_kernel, cudaFuncAttributeMaxDynamicSharedMemorySize, SMEM_BYTES);

    dim3 grid(HH, BATCH);   // 64 x 4 = 256 blocks, one per (y, b)
    corr_kernel<<<grid, NTHREADS, SMEM_BYTES>>>(in1, in2, out);
}